// round 16
// baseline (speedup 1.0000x reference)
#include <cuda_runtime.h>

#define NN 100000
#define EE 1600000
#define GG 64

typedef unsigned long long u64;

// ---------------- packed f32x2 helpers ----------------
__device__ __forceinline__ u64 pack2(float lo, float hi) {
    u64 r; asm("mov.b64 %0, {%1, %2};" : "=l"(r) : "f"(lo), "f"(hi)); return r;
}
__device__ __forceinline__ void ffma2(u64& d, u64 a, u64 b) {
    asm("fma.rn.f32x2 %0, %1, %2, %3;" : "=l"(d) : "l"(a), "l"(b), "l"(d));
}
__device__ __forceinline__ void unpack2(u64 v, float& lo, float& hi) {
    asm("mov.b64 {%0, %1}, %2;" : "=f"(lo), "=f"(hi) : "l"(v));
}

// ---------------- scratch ----------------
__device__ int   g_cnt[NN];
__device__ int   g_rowptr[NN + 1];
__device__ int   g_cursor[NN];
__device__ int   g_eidx[EE];
__device__ float g_agg[(size_t)NN * 128];   // holds MEAN (deg folded in)
__device__ float g_x1[(size_t)NN * 128];
__device__ float g_x2[(size_t)NN * 128];
__device__ float g_pool[GG * 256];

// ---------------- zero / count ----------------
__global__ void zero_cnt_kernel() {
    int i = blockIdx.x * blockDim.x + threadIdx.x;
    if (i < NN) g_cnt[i] = 0;
}

__global__ void zero_pool_kernel() {
    int i = blockIdx.x * blockDim.x + threadIdx.x;
    if (i < GG * 256) g_pool[i] = 0.f;
}

__global__ void count_kernel(const int* __restrict__ dst, int e) {
    int i = blockIdx.x * blockDim.x + threadIdx.x;
    if (i < e) atomicAdd(&g_cnt[dst[i]], 1);
}

// ---------------- single-block prefix scan: counts -> rowptr/cursor ----------
__global__ void __launch_bounds__(1024) scan_kernel() {
    __shared__ int sums[1024];
    const int CH = (NN + 1023) / 1024;   // 98
    int t = threadIdx.x;
    int beg = t * CH, end = min(beg + CH, NN);

    int local = 0;
    for (int i = beg; i < end; i++) local += g_cnt[i];
    sums[t] = local;
    __syncthreads();

    // Hillis-Steele inclusive scan over 1024 entries
#pragma unroll
    for (int ofs = 1; ofs < 1024; ofs <<= 1) {
        int v = sums[t];
        int u = (t >= ofs) ? sums[t - ofs] : 0;
        __syncthreads();
        sums[t] = v + u;
        __syncthreads();
    }
    int run = (t == 0) ? 0 : sums[t - 1];  // exclusive prefix

    for (int i = beg; i < end; i++) {
        g_rowptr[i] = run;
        g_cursor[i] = run;
        run += g_cnt[i];
    }
    if (end == NN && beg <= NN) g_rowptr[NN] = run;
}

// ---------------- CSR fill: edge id -> per-dst list --------------------------
__global__ void fill_kernel(const int* __restrict__ src,
                            const int* __restrict__ dst, int e) {
    int i = blockIdx.x * blockDim.x + threadIdx.x;
    if (i >= e) return;
    int d = dst[i];
    int pos = atomicAdd(&g_cursor[d], 1);
    g_eidx[pos] = src[i];
}

// ---------------- gather 7-dim mean: 7 threads per node ----------------------
__global__ void __launch_bounds__(224) gather7_kernel(const float* __restrict__ x) {
    int node = blockIdx.x * 32 + threadIdx.x / 7;
    int k = threadIdx.x % 7;
    if (node >= NN) return;
    int beg = g_rowptr[node], end = g_rowptr[node + 1];
    float acc = 0.f;
    for (int e = beg; e < end; e++)
        acc += x[(size_t)g_eidx[e] * 7 + k];
    g_agg[(size_t)node * 7 + k] = acc / (float)max(end - beg, 1);
}

// ---------------- layer 0 fused: x@Wl + bl + mean@Wr -> BN -> ReLU -> g_x1 ----
__global__ void __launch_bounds__(128) layer0_kernel(
    const float* __restrict__ x,
    const float* __restrict__ Wl, const float* __restrict__ bl,
    const float* __restrict__ Wr,
    const float* __restrict__ gma, const float* __restrict__ bet,
    const float* __restrict__ rm, const float* __restrict__ rv, int n)
{
    int j = threadIdx.x;  // output column
    float wl[7], wr[7];
#pragma unroll
    for (int k = 0; k < 7; k++) { wl[k] = Wl[k * 128 + j]; wr[k] = Wr[k * 128 + j]; }
    float sc = gma[j] * rsqrtf(rv[j] + 1e-5f);
    float of = bet[j] + (bl[j] - rm[j]) * sc;

    int i0 = blockIdx.x * 64;
    int iend = min(i0 + 64, n);
    for (int i = i0; i < iend; i++) {
        const float* xr = x + (size_t)i * 7;
        const float* ar = g_agg + (size_t)i * 7;   // mean already
        float acc = 0.f;
#pragma unroll
        for (int k = 0; k < 7; k++) acc += xr[k] * wl[k] + ar[k] * wr[k];
        g_x1[(size_t)i * 128 + j] = fmaxf(acc * sc + of, 0.f);
    }
}

// ---------------- gather 128-dim mean: warp per node -------------------------
template <int SRC>
__global__ void __launch_bounds__(256) gather128_kernel() {
    const float* x;
    if constexpr (SRC == 1) x = g_x1; else x = g_x2;
    int warp = (blockIdx.x * blockDim.x + threadIdx.x) >> 5;
    int lane = threadIdx.x & 31;
    if (warp >= NN) return;
    int beg = g_rowptr[warp], end = g_rowptr[warp + 1];

    float4 acc0 = make_float4(0.f, 0.f, 0.f, 0.f);
    float4 acc1 = make_float4(0.f, 0.f, 0.f, 0.f);
    int e = beg;
    for (; e + 2 <= end; e += 2) {
        int s0 = g_eidx[e], s1 = g_eidx[e + 1];
        float4 v0 = *(const float4*)(x + (size_t)s0 * 128 + lane * 4);
        float4 v1 = *(const float4*)(x + (size_t)s1 * 128 + lane * 4);
        acc0.x += v0.x; acc0.y += v0.y; acc0.z += v0.z; acc0.w += v0.w;
        acc1.x += v1.x; acc1.y += v1.y; acc1.z += v1.z; acc1.w += v1.w;
    }
    if (e < end) {
        int s0 = g_eidx[e];
        float4 v0 = *(const float4*)(x + (size_t)s0 * 128 + lane * 4);
        acc0.x += v0.x; acc0.y += v0.y; acc0.z += v0.z; acc0.w += v0.w;
    }
    float iv = 1.f / (float)max(end - beg, 1);
    float4 r;
    r.x = (acc0.x + acc1.x) * iv;
    r.y = (acc0.y + acc1.y) * iv;
    r.z = (acc0.z + acc1.z) * iv;
    r.w = (acc0.w + acc1.w) * iv;
    *(float4*)(g_agg + (size_t)warp * 128 + lane * 4) = r;
}

// ---------------- fused GEMM: [x | mean] @ [Wl ; Wr] + bl -> BN -> ReLU ------
// BM=128, BN=128, BK=16; 256 threads; 8x8 per thread; FFMA2 inner loop with
// B pre-duplicated into f32x2 pairs at tile-load time.
// SRC: 1 -> g_x1, 2 -> g_x2.  DSTSEL: 1 -> g_x2, 0 -> out param.
template <int DOUT, int SRC, int DSTSEL>
__global__ void __launch_bounds__(256) sage_gemm_bn_relu(
    const float* __restrict__ Wl, const float* __restrict__ Wr,
    const float* __restrict__ bl,
    const float* __restrict__ gma, const float* __restrict__ bet,
    const float* __restrict__ rm, const float* __restrict__ rv,
    float* __restrict__ out, int n)
{
    const float* x;
    if constexpr (SRC == 1) x = g_x1; else x = g_x2;

    constexpr int BM = 128, BN = 128, BK = 16;
    constexpr int ASTRIDE = BM + 4;
    __shared__ float As[BK][ASTRIDE];
    __shared__ u64   Bs2[BK][BN];      // each entry: col value duplicated

    int t = threadIdx.x;
    int tx = t & 15;          // 0..15 -> 8 cols each
    int ty = t >> 4;          // 0..15 -> 8 rows (4 pairs) each
    int m0 = blockIdx.x * BM;
    int n0 = blockIdx.y * BN;

    u64 acc2[4][8];
#pragma unroll
    for (int r = 0; r < 4; r++)
#pragma unroll
        for (int c = 0; c < 8; c++) acc2[r][c] = 0ull;

    int a_k4 = (t & 3) * 4;
    int a_row = t >> 2;       // 0..63 (+64 second half)
    int b_j4 = (t & 15) * 4;
    int b_kk = t >> 4;        // 0..15

#pragma unroll 1
    for (int kt = 0; kt < 256 / BK; ++kt) {
        int k0 = kt * BK;
        const float* Asrc = (k0 < 128) ? x : (const float*)g_agg;
        int klocal = (k0 < 128) ? k0 : (k0 - 128);

        // A tile (transposed)
#pragma unroll
        for (int h = 0; h < 2; ++h) {
            int row = a_row + h * 64;
            int grow = m0 + row;
            float4 v = make_float4(0.f, 0.f, 0.f, 0.f);
            if (grow < n)
                v = *(const float4*)(Asrc + (size_t)grow * 128 + klocal + a_k4);
            As[a_k4 + 0][row] = v.x;
            As[a_k4 + 1][row] = v.y;
            As[a_k4 + 2][row] = v.z;
            As[a_k4 + 3][row] = v.w;
        }
        // B tile: 16 k x 128 cols, duplicated-pack once
        {
            const float* W = (k0 < 128) ? Wl : Wr;
#pragma unroll
            for (int h = 0; h < 2; ++h) {
                int j = b_j4 + h * 64;
                float4 v = *(const float4*)(W + (size_t)(klocal + b_kk) * DOUT + n0 + j);
                Bs2[b_kk][j + 0] = pack2(v.x, v.x);
                Bs2[b_kk][j + 1] = pack2(v.y, v.y);
                Bs2[b_kk][j + 2] = pack2(v.z, v.z);
                Bs2[b_kk][j + 3] = pack2(v.w, v.w);
            }
        }
        __syncthreads();

#pragma unroll
        for (int kk = 0; kk < BK; ++kk) {
            u64 a2[4];
            {
                const ulonglong2* ap = (const ulonglong2*)&As[kk][ty * 8];
                ulonglong2 p0 = ap[0], p1 = ap[1];
                a2[0] = p0.x; a2[1] = p0.y; a2[2] = p1.x; a2[3] = p1.y;
            }
            u64 b2[8];
            {
                const ulonglong2* bp = (const ulonglong2*)&Bs2[kk][tx * 8];
                ulonglong2 q0 = bp[0], q1 = bp[1], q2 = bp[2], q3 = bp[3];
                b2[0] = q0.x; b2[1] = q0.y; b2[2] = q1.x; b2[3] = q1.y;
                b2[4] = q2.x; b2[5] = q2.y; b2[6] = q3.x; b2[7] = q3.y;
            }
#pragma unroll
            for (int r = 0; r < 4; r++)
#pragma unroll
                for (int c = 0; c < 8; c++) ffma2(acc2[r][c], a2[r], b2[c]);
        }
        __syncthreads();
    }

    // epilogue: folded BN + ReLU
    float s[8], o[8];
#pragma unroll
    for (int c = 0; c < 8; c++) {
        int j = n0 + tx * 8 + c;
        float sc = gma[j] * rsqrtf(rv[j] + 1e-5f);
        s[c] = sc;
        o[c] = bet[j] + (bl[j] - rm[j]) * sc;
    }

    float* dstp;
    if constexpr (DSTSEL == 1) dstp = g_x2; else dstp = out;

#pragma unroll
    for (int r2 = 0; r2 < 4; r2++) {
#pragma unroll
        for (int half = 0; half < 2; half++) {
            int grow = m0 + ty * 8 + r2 * 2 + half;
            if (grow < n) {
#pragma unroll
                for (int c = 0; c < 8; c++) {
                    float lo, hi;
                    unpack2(acc2[r2][c], lo, hi);
                    float a = half ? hi : lo;
                    dstp[(size_t)grow * DOUT + n0 + tx * 8 + c] =
                        fmaxf(a * s[c] + o[c], 0.f);
                }
            }
        }
    }
}

// ---------------- global add pool (batch is sorted) --------------------------
__global__ void __launch_bounds__(256) pool_kernel(
    const int* __restrict__ batch,
    const float* __restrict__ x3,  // [n,256]
    int n)
{
    int col = threadIdx.x;
    int i0 = blockIdx.x * 64;
    if (i0 >= n) return;
    int iend = min(i0 + 64, n);
    int cur = batch[i0];
    float acc = 0.f;
    for (int i = i0; i < iend; i++) {
        int b = batch[i];
        if (b != cur) {
            atomicAdd(&g_pool[(size_t)cur * 256 + col], acc);
            acc = 0.f;
            cur = b;
        }
        acc += x3[(size_t)i * 256 + col];
    }
    atomicAdd(&g_pool[(size_t)cur * 256 + col], acc);
}

__global__ void copy_pool_kernel(float* __restrict__ out) {
    int i = blockIdx.x * blockDim.x + threadIdx.x;
    if (i < GG * 256) out[i] = g_pool[i];
}

// ---------------- launch ----------------
extern "C" void kernel_launch(void* const* d_in, const int* in_sizes, int n_in,
                              void* d_out, int out_size)
{
    const float* x     = (const float*)d_in[0];
    const int*   ei    = (const int*)d_in[1];    // int32
    const int*   batch = (const int*)d_in[2];    // int32

    const float *Wl0=(const float*)d_in[3],  *bl0=(const float*)d_in[4],  *Wr0=(const float*)d_in[5];
    const float *g0 =(const float*)d_in[6],  *be0=(const float*)d_in[7],  *rm0=(const float*)d_in[8],  *rv0=(const float*)d_in[9];
    const float *Wl1=(const float*)d_in[10], *bl1=(const float*)d_in[11], *Wr1=(const float*)d_in[12];
    const float *g1 =(const float*)d_in[13], *be1=(const float*)d_in[14], *rm1=(const float*)d_in[15], *rv1=(const float*)d_in[16];
    const float *Wl2=(const float*)d_in[17], *bl2=(const float*)d_in[18], *Wr2=(const float*)d_in[19];
    const float *g2 =(const float*)d_in[20], *be2=(const float*)d_in[21], *rm2=(const float*)d_in[22], *rv2=(const float*)d_in[23];

    const int* src = ei;
    const int* dst = ei + EE;

    float* out_pooled = (float*)d_out;
    float* out_x      = (float*)d_out + (size_t)GG * 256;

    // ---- CSR build ----
    zero_cnt_kernel<<<(NN + 255) / 256, 256>>>();
    count_kernel<<<(EE + 255) / 256, 256>>>(dst, EE);
    scan_kernel<<<1, 1024>>>();
    fill_kernel<<<(EE + 255) / 256, 256>>>(src, dst, EE);

    // ---- layer 0 (7 -> 128) ----
    gather7_kernel<<<(NN + 31) / 32, 224>>>(x);
    layer0_kernel<<<(NN + 63) / 64, 128>>>(x, Wl0, bl0, Wr0, g0, be0, rm0, rv0, NN);

    // ---- layer 1 (128 -> 128) ----
    gather128_kernel<1><<<(NN * 32 + 255) / 256, 256>>>();
    sage_gemm_bn_relu<128, 1, 1><<<dim3((NN + 127) / 128, 1), 256>>>(
        Wl1, Wr1, bl1, g1, be1, rm1, rv1, out_x, NN);

    // ---- layer 2 (128 -> 256) ----
    gather128_kernel<2><<<(NN * 32 + 255) / 256, 256>>>();
    sage_gemm_bn_relu<256, 2, 0><<<dim3((NN + 127) / 128, 2), 256>>>(
        Wl2, Wr2, bl2, g2, be2, rm2, rv2, out_x, NN);

    // ---- global add pool ----
    zero_pool_kernel<<<(GG * 256 + 255) / 256, 256>>>();
    pool_kernel<<<(NN + 63) / 64, 256>>>(batch, out_x, NN);
    copy_pool_kernel<<<(GG * 256 + 255) / 256, 256>>>(out_pooled);
}